// round 8
// baseline (speedup 1.0000x reference)
#include <cuda_runtime.h>
#include <math_constants.h>
#include <cstdint>

// Problem shape (fixed)
#define Bdim 2048
#define Ddim 25088
#define Cdim 100
#define CPAD 128

#define SPLITS 8
#define KC (Ddim / SPLITS)      // 3136
#define KT 64                   // fp16 K per iteration
#define ITERS (KC / KT)         // 49
#define BM 128

// smem slot: A tile (128 x 64 fp16, STR=144) + B tile (same)
#define STR 144
#define TILE_SZ (128 * STR)              // 18432 B
#define SLOT_SZ (2 * TILE_SZ)            // 36864 B
#define NSLOT 4
#define SMEM_TOTAL (NSLOT * SLOT_SZ)     // 147456 B

#define W32 12544                        // u32 per W row (25088 fp16)

// ---------------- scratch ----------------
__device__ float    g_part[(size_t)SPLITS * Bdim * CPAD];  // 8 MB split partials
__device__ float    g_nfsq[SPLITS * Bdim];                 // feature norm^2 partials
__device__ uint32_t g_wh[(size_t)CPAD * W32];              // normalized W, fp16
__device__ unsigned long long g_loss_fx;                   // fixed-point loss sum (2^-32)
__device__ int      g_corr_acc;
__device__ int      g_vld_acc;
__device__ unsigned g_ticket;

// ---------------- helpers ----------------
__device__ __forceinline__ uint32_t smem_u32(const void* p) {
    uint32_t a;
    asm("{ .reg .u64 t; cvta.to.shared.u64 t, %1; cvt.u32.u64 %0, t; }" : "=r"(a) : "l"(p));
    return a;
}
__device__ __forceinline__ void ldsm4(uint32_t addr, uint32_t& r0, uint32_t& r1,
                                      uint32_t& r2, uint32_t& r3) {
    asm volatile("ldmatrix.sync.aligned.m8n8.x4.shared.b16 {%0,%1,%2,%3}, [%4];"
                 : "=r"(r0), "=r"(r1), "=r"(r2), "=r"(r3) : "r"(addr));
}
__device__ __forceinline__ void mma_f16(float& d0, float& d1, float& d2, float& d3,
                                        uint32_t a0, uint32_t a1, uint32_t a2, uint32_t a3,
                                        uint32_t b0, uint32_t b1) {
    asm volatile("mma.sync.aligned.m16n8k16.row.col.f32.f16.f16.f32 "
                 "{%0,%1,%2,%3}, {%4,%5,%6,%7}, {%8,%9}, {%0,%1,%2,%3};"
                 : "+f"(d0), "+f"(d1), "+f"(d2), "+f"(d3)
                 : "r"(a0), "r"(a1), "r"(a2), "r"(a3), "r"(b0), "r"(b1));
}
__device__ __forceinline__ uint32_t cvt_f16x2(float x, float y) {
    uint32_t r;
    asm("cvt.rn.f16x2.f32 %0, %1, %2;" : "=r"(r) : "f"(y), "f"(x));
    return r;
}
#define CP16(dst, src) asm volatile("cp.async.cg.shared.global [%0], [%1], 16;" :: "r"(dst), "l"(src))
#define CP_COMMIT()    asm volatile("cp.async.commit_group;" ::: "memory")
#define CP_WAIT0()     asm volatile("cp.async.wait_group 0;" ::: "memory")
#define BAR_SYNC(id)   asm volatile("bar.sync %0, 512;"   :: "r"(id) : "memory")
#define BAR_ARRIVE(id) asm volatile("bar.arrive %0, 512;" :: "r"(id) : "memory")
// FULL barrier ids 1..4, EMPTY ids 5..8 (slot s -> 1+s / 5+s)

// ======================= W prep: norm + normalize + fp16 (+acc zeroing) ========
__global__ __launch_bounds__(256) void prep_w_kernel(const float* __restrict__ W) {
    const int row = blockIdx.x;                // 0..127
    const int t   = threadIdx.x;
    __shared__ float red[256];
    __shared__ float s_inv;

    if (row == 0 && t == 0) {
        g_loss_fx = 0ull; g_corr_acc = 0; g_vld_acc = 0; g_ticket = 0u;
    }

    uint32_t* dh = &g_wh[(size_t)row * W32];
    if (row < Cdim) {
        const float4* r4 = (const float4*)(W + (size_t)row * Ddim);
        float s = 0.f;
        for (int i = t; i < Ddim / 4; i += 256) {
            float4 v = r4[i];
            s += v.x * v.x + v.y * v.y + v.z * v.z + v.w * v.w;
        }
        red[t] = s;
        __syncthreads();
        for (int off = 128; off > 0; off >>= 1) {
            if (t < off) red[t] += red[t + off];
            __syncthreads();
        }
        if (t == 0) s_inv = 1.0f / fmaxf(sqrtf(red[0]), 1e-8f);
        __syncthreads();
        const float inv = s_inv;
        const float2* r2 = (const float2*)(W + (size_t)row * Ddim);
        for (int i = t; i < W32; i += 256) {
            float2 v = r2[i];
            dh[i] = cvt_f16x2(v.x * inv, v.y * inv);
        }
    } else {
        for (int i = t; i < W32; i += 256) dh[i] = 0u;
    }
}

// ======================= warp-specialized HMMA fp16 GEMM =======================
// grid (Bdim/BM, SPLITS), 512 threads.
// Warps 0-11 consumers: wm = w&3 (SMSP), wn = w>>2 in {0,1,2}.
//   wn covers n16 groups at cols {wn*32, wn*32+16} (+ lone n8 at col 96 for wn==0).
// Warps 12-15 producers: thread pt = t-384 owns feature row pt and W row pt.
__global__ void __launch_bounds__(512, 1)
gemm_mma_kernel(const float* __restrict__ F) {
    extern __shared__ char smem[];
    const uint32_t sbase = smem_u32(smem);

    const int t     = threadIdx.x;
    const int lane  = t & 31;
    const int w     = t >> 5;
    const int m0    = blockIdx.x * BM;
    const int split = blockIdx.y;
    const int k0    = split * KC;

    if (w >= 12) {
        // ===================== PRODUCER =====================
        const int pt = t - 384;                // 0..127 (row)
        const float4* gA = (const float4*)(F + (size_t)(m0 + pt) * Ddim + k0);
        const char* srcB = (const char*)g_wh + (size_t)pt * (W32 * 4) + (size_t)k0 * 2;
        const uint32_t stsA = pt * STR;                 // A at slot base + 0
        const uint32_t dstB = TILE_SZ + pt * STR;       // B at slot base + TILE_SZ

        float nf = 0.f;

        for (int it = 0; it < ITERS; it++) {
            const int slot = it & 3;
            const uint32_t sb = sbase + slot * SLOT_SZ;

            if (it >= NSLOT) BAR_SYNC(5 + slot);        // wait consumers freed slot

            // B: 128 B row via 8x cp.async
            const char* s = srcB + (size_t)it * 128;
#pragma unroll
            for (int c = 0; c < 8; c++) CP16(sb + dstB + c * 16, s + c * 16);
            CP_COMMIT();

            // A: 64 floats -> 32 f16x2 -> 8 STS.128
            float4 v[16];
#pragma unroll
            for (int j = 0; j < 16; j++) v[j] = gA[it * 16 + j];
#pragma unroll
            for (int c = 0; c < 4; c++) {
                uint32_t pk[8];
#pragma unroll
                for (int j = 0; j < 4; j++) {
                    float4 x = v[c * 4 + j];
                    nf += x.x * x.x + x.y * x.y + x.z * x.z + x.w * x.w;
                    pk[2 * j]     = cvt_f16x2(x.x, x.y);
                    pk[2 * j + 1] = cvt_f16x2(x.z, x.w);
                }
                *(uint4*)(smem + slot * SLOT_SZ + stsA + c * 32)      =
                    make_uint4(pk[0], pk[1], pk[2], pk[3]);
                *(uint4*)(smem + slot * SLOT_SZ + stsA + c * 32 + 16) =
                    make_uint4(pk[4], pk[5], pk[6], pk[7]);
            }

            CP_WAIT0();                // B in smem
            BAR_ARRIVE(1 + slot);      // slot full
        }
        g_nfsq[split * Bdim + m0 + pt] = nf;
        return;
    }

    // ===================== CONSUMER =====================
    const int wm = w & 3;
    const int wn = w >> 2;             // 0..2
    const bool has3 = (wn == 0);       // lone n8 group at col 96

    const uint32_t aRel  = (wm * 32 + (lane & 15)) * STR + (lane >> 4) * 16;
    const uint32_t bLane = (lane & 7) + ((lane >> 4) << 3);
    const uint32_t bOff  = (((lane >> 3) & 1) << 4);
    const uint32_t bRel01 = TILE_SZ + (wn * 32 + bLane) * STR + bOff;
    const uint32_t bRel2  = TILE_SZ + (96 + bLane) * STR + bOff;

    float acc[2][5][4];
#pragma unroll
    for (int i = 0; i < 2; i++)
#pragma unroll
        for (int j = 0; j < 5; j++)
#pragma unroll
            for (int e = 0; e < 4; e++) acc[i][j][e] = 0.f;

    for (int it = 0; it < ITERS; it++) {
        const int slot = it & 3;
        const uint32_t sb = sbase + slot * SLOT_SZ;

        BAR_SYNC(1 + slot);            // wait slot full

#pragma unroll
        for (int ks = 0; ks < 4; ks++) {
            uint32_t ah[2][4], bh[2][4], b2[4];
#pragma unroll
            for (int mi = 0; mi < 2; mi++)
                ldsm4(sb + aRel + mi * 16 * STR + ks * 32,
                      ah[mi][0], ah[mi][1], ah[mi][2], ah[mi][3]);
            ldsm4(sb + bRel01 + ks * 32, bh[0][0], bh[0][1], bh[0][2], bh[0][3]);
            ldsm4(sb + bRel01 + 16 * STR + ks * 32, bh[1][0], bh[1][1], bh[1][2], bh[1][3]);
            if (has3)
                ldsm4(sb + bRel2 + ks * 32, b2[0], b2[1], b2[2], b2[3]);

#pragma unroll
            for (int mi = 0; mi < 2; mi++) {
#pragma unroll
                for (int g = 0; g < 2; g++)
#pragma unroll
                    for (int h = 0; h < 2; h++) {
                        float* d = acc[mi][g * 2 + h];
                        mma_f16(d[0], d[1], d[2], d[3],
                                ah[mi][0], ah[mi][1], ah[mi][2], ah[mi][3],
                                bh[g][2 * h], bh[g][2 * h + 1]);
                    }
                if (has3) {
                    float* d = acc[mi][4];
                    mma_f16(d[0], d[1], d[2], d[3],
                            ah[mi][0], ah[mi][1], ah[mi][2], ah[mi][3],
                            b2[0], b2[1]);
                }
            }
        }

        BAR_ARRIVE(5 + slot);          // slot empty
    }

    // write live partials
    const int njmax = has3 ? 5 : 4;
#pragma unroll
    for (int mi = 0; mi < 2; mi++)
#pragma unroll
        for (int nj = 0; nj < 5; nj++) {
            if (nj >= njmax) break;
            const int colb = (nj < 4) ? (wn * 32 + nj * 8) : 96;
#pragma unroll
            for (int e = 0; e < 4; e++) {
                const int r = m0 + wm * 32 + mi * 16 + (lane >> 2) + (e >> 1) * 8;
                const int c = colb + (lane & 3) * 2 + (e & 1);
                g_part[((size_t)split * Bdim + r) * CPAD + c] = acc[mi][nj][e];
            }
        }
}

// ======================= per-row epilogue + fused finalize =======================
__global__ __launch_bounds__(128) void epilogue_kernel(const void* __restrict__ labels,
                                                       float* __restrict__ out,
                                                       int out_size) {
    const int row = blockIdx.x;
    const int t   = threadIdx.x;

    __shared__ float sv[128];
    __shared__ int   si[128];
    __shared__ float slog[128];
    __shared__ float s_nf;
    __shared__ int   s_ok[2];
    __shared__ unsigned s_tick;

    // int64-vs-int32 label layout sniff
    if (t < 64) {
        const int hi = ((const int*)labels)[2 * t + 1];
        const int ok = (hi == 0 || hi == -1) ? 1 : 0;
        unsigned b = __ballot_sync(0xFFFFFFFFu, ok);
        if ((t & 31) == 0) s_ok[t >> 5] = (b == 0xFFFFFFFFu);
    }

    // feature-norm reduction (warp 2, 8 partials)
    if (t >= 64 && t < 96) {
        const int l = t - 64;
        float s = (l < SPLITS) ? g_nfsq[l * Bdim + row] : 0.f;
#pragma unroll
        for (int off = 16; off > 0; off >>= 1)
            s += __shfl_down_sync(0xFFFFFFFFu, s, off);
        if (l == 0) s_nf = fmaxf(sqrtf(s), 1e-8f);
    }

    float g = 0.f;
    if (t < Cdim) {
#pragma unroll
        for (int s = 0; s < SPLITS; s++)
            g += g_part[((size_t)s * Bdim + row) * CPAD + t];
    }
    __syncthreads();

    const float logit = (t < Cdim) ? 10.0f * g / s_nf : -CUDART_INF_F;
    slog[t] = logit;
    sv[t]   = logit;
    si[t]   = t;
    __syncthreads();

    for (int off = 64; off > 0; off >>= 1) {
        if (t < off) {
            float v2 = sv[t + off]; int i2 = si[t + off];
            if (v2 > sv[t] || (v2 == sv[t] && i2 < si[t])) { sv[t] = v2; si[t] = i2; }
        }
        __syncthreads();
    }
    const float mx   = sv[0];
    const int   amax = si[0];
    __syncthreads();

    sv[t] = (t < Cdim) ? expf(logit - mx) : 0.f;
    __syncthreads();
    for (int off = 64; off > 0; off >>= 1) {
        if (t < off) sv[t] += sv[t + off];
        __syncthreads();
    }

    if (t == 0) {
        const float lse = logf(sv[0]) + mx;
        const int is64 = (s_ok[0] && s_ok[1]) ? 1 : 0;
        long long lab;
        if (is64) lab = ((const long long*)labels)[row];
        else      lab = (long long)((const int*)labels)[row];
        if (lab >= 0) {
            const float nll = lse - slog[(int)lab];
            // fixed-point (2^-32) integer accumulate: order-independent, deterministic
            const unsigned long long fx =
                (unsigned long long)(fmax((double)nll, 0.0) * 4294967296.0 + 0.5);
            atomicAdd(&g_loss_fx, fx);
            if (amax == (int)lab) atomicAdd(&g_corr_acc, 1);
            atomicAdd(&g_vld_acc, 1);
        }
        __threadfence();
        s_tick = atomicAdd(&g_ticket, 1u);
    }
    __syncthreads();

    // last block finalizes
    if (s_tick == (unsigned)(gridDim.x - 1) && t == 0) {
        const double loss_sum = (double)g_loss_fx * (1.0 / 4294967296.0);
        const float nv = (float)g_vld_acc;
        out[0] = (float)(loss_sum / (double)fmaxf(nv, 1.0f));
        if (out_size > 1) out[1] = (float)g_corr_acc / (nv + 1e-10f);
    }
}

// ======================= launch =======================
extern "C" void kernel_launch(void* const* d_in, const int* in_sizes, int n_in,
                              void* d_out, int out_size) {
    int fi = 0, li = 0;
    for (int i = 1; i < n_in; i++) {
        if (in_sizes[i] > in_sizes[fi]) fi = i;
        if (in_sizes[i] < in_sizes[li]) li = i;
    }
    int wi = 0;
    for (int i = 0; i < n_in; i++) if (i != fi && i != li) wi = i;

    const float* F = (const float*)d_in[fi];
    const float* W = (const float*)d_in[wi];
    const void*  L = d_in[li];

    cudaFuncSetAttribute(gemm_mma_kernel,
                         cudaFuncAttributeMaxDynamicSharedMemorySize, SMEM_TOTAL);

    prep_w_kernel<<<CPAD, 256>>>(W);
    gemm_mma_kernel<<<dim3(Bdim / BM, SPLITS), 512, SMEM_TOTAL>>>(F);
    epilogue_kernel<<<Bdim, 128>>>(L, (float*)d_out, out_size);
}

// round 9
// speedup vs baseline: 1.1759x; 1.1759x over previous
#include <cuda_runtime.h>
#include <math_constants.h>
#include <cstdint>

// Problem shape (fixed)
#define Bdim 2048
#define Ddim 25088
#define Cdim 100
#define CPAD 128

#define SPLITS 8
#define KC (Ddim / SPLITS)      // 3136
#define KT 64                   // fp16 K per iteration
#define ITERS (KC / KT)         // 49
#define BM 128

// smem slot: A tile (128 x 64 fp16, STR=144) + B tile (same)
#define STR 144
#define TILE_SZ (128 * STR)              // 18432 B
#define SLOT_SZ (2 * TILE_SZ)            // 36864 B
#define NSLOT 4
#define SMEM_TOTAL (NSLOT * SLOT_SZ)     // 147456 B

#define W32 12544                        // u32 per W row (25088 fp16)

// ---------------- scratch ----------------
__device__ float    g_part[(size_t)SPLITS * Bdim * CPAD];  // 8 MB split partials
__device__ float    g_nfsq[SPLITS * 2 * Bdim];             // feature norm^2 partials
__device__ uint32_t g_wh[(size_t)CPAD * W32];              // normalized W, fp16
__device__ unsigned long long g_loss_fx;                   // fixed-point loss sum (2^-32)
__device__ int      g_corr_acc;
__device__ int      g_vld_acc;
__device__ unsigned g_ticket;

// ---------------- helpers ----------------
__device__ __forceinline__ uint32_t smem_u32(const void* p) {
    uint32_t a;
    asm("{ .reg .u64 t; cvta.to.shared.u64 t, %1; cvt.u32.u64 %0, t; }" : "=r"(a) : "l"(p));
    return a;
}
__device__ __forceinline__ void ldsm4(uint32_t addr, uint32_t& r0, uint32_t& r1,
                                      uint32_t& r2, uint32_t& r3) {
    asm volatile("ldmatrix.sync.aligned.m8n8.x4.shared.b16 {%0,%1,%2,%3}, [%4];"
                 : "=r"(r0), "=r"(r1), "=r"(r2), "=r"(r3) : "r"(addr));
}
__device__ __forceinline__ void mma_f16(float& d0, float& d1, float& d2, float& d3,
                                        uint32_t a0, uint32_t a1, uint32_t a2, uint32_t a3,
                                        uint32_t b0, uint32_t b1) {
    asm volatile("mma.sync.aligned.m16n8k16.row.col.f32.f16.f16.f32 "
                 "{%0,%1,%2,%3}, {%4,%5,%6,%7}, {%8,%9}, {%0,%1,%2,%3};"
                 : "+f"(d0), "+f"(d1), "+f"(d2), "+f"(d3)
                 : "r"(a0), "r"(a1), "r"(a2), "r"(a3), "r"(b0), "r"(b1));
}
__device__ __forceinline__ uint32_t cvt_f16x2(float x, float y) {
    uint32_t r;
    asm("cvt.rn.f16x2.f32 %0, %1, %2;" : "=r"(r) : "f"(y), "f"(x));
    return r;
}
#define CP16(dst, src) asm volatile("cp.async.cg.shared.global [%0], [%1], 16;" :: "r"(dst), "l"(src))
#define CP_COMMIT()    asm volatile("cp.async.commit_group;" ::: "memory")
#define CP_WAIT0()     asm volatile("cp.async.wait_group 0;" ::: "memory")
#define BAR_SYNC(id)   asm volatile("bar.sync %0, 512;"   :: "r"(id) : "memory")
#define BAR_ARRIVE(id) asm volatile("bar.arrive %0, 512;" :: "r"(id) : "memory")
// FULL barrier ids 1..4, EMPTY ids 5..8 (slot s -> 1+s / 5+s)

// ======================= W prep: norm + normalize + fp16 (+acc zeroing) ========
__global__ __launch_bounds__(1024) void prep_w_kernel(const float* __restrict__ W) {
    const int row = blockIdx.x;                // 0..127
    const int t   = threadIdx.x;
    __shared__ float red[1024];
    __shared__ float s_inv;

    if (row == 0 && t == 0) {
        g_loss_fx = 0ull; g_corr_acc = 0; g_vld_acc = 0; g_ticket = 0u;
    }

    uint32_t* dh = &g_wh[(size_t)row * W32];
    if (row < Cdim) {
        const float4* r4 = (const float4*)(W + (size_t)row * Ddim);
        float s = 0.f;
        for (int i = t; i < Ddim / 4; i += 1024) {
            float4 v = r4[i];
            s += v.x * v.x + v.y * v.y + v.z * v.z + v.w * v.w;
        }
        red[t] = s;
        __syncthreads();
        for (int off = 512; off > 0; off >>= 1) {
            if (t < off) red[t] += red[t + off];
            __syncthreads();
        }
        if (t == 0) s_inv = 1.0f / fmaxf(sqrtf(red[0]), 1e-8f);
        __syncthreads();
        const float inv = s_inv;
        const float2* r2 = (const float2*)(W + (size_t)row * Ddim);
        for (int i = t; i < W32; i += 1024) {
            float2 v = r2[i];
            dh[i] = cvt_f16x2(v.x * inv, v.y * inv);
        }
    } else {
        for (int i = t; i < W32; i += 1024) dh[i] = 0u;
    }
}

// ---------------- consumer inner loop (templated tile count) ----------------
template <int NT>   // 6 (wn=0) or 7 (wn=1, incl. lone n8 @ col 96)
__device__ __forceinline__ void consumer_loop(
    const uint32_t sbase, const uint32_t aRel, const uint32_t bRelBase,
    const uint32_t bRelLone, const int m0, const int split,
    const int wm, const int wn, const int lane)
{
    float acc[2][NT][4];
#pragma unroll
    for (int i = 0; i < 2; i++)
#pragma unroll
        for (int j = 0; j < NT; j++)
#pragma unroll
            for (int e = 0; e < 4; e++) acc[i][j][e] = 0.f;

    for (int it = 0; it < ITERS; it++) {
        const int slot = it & 3;
        const uint32_t sb = sbase + slot * SLOT_SZ;

        BAR_SYNC(1 + slot);            // wait slot full

#pragma unroll
        for (int ks = 0; ks < 4; ks++) {
            uint32_t ah[2][4];
#pragma unroll
            for (int mi = 0; mi < 2; mi++)
                ldsm4(sb + aRel + mi * 16 * STR + ks * 32,
                      ah[mi][0], ah[mi][1], ah[mi][2], ah[mi][3]);

            uint32_t bh[3][4], b2[4];
#pragma unroll
            for (int g = 0; g < 3; g++)
                ldsm4(sb + bRelBase + g * 16 * STR + ks * 32,
                      bh[g][0], bh[g][1], bh[g][2], bh[g][3]);
            if (NT == 7)
                ldsm4(sb + bRelLone + ks * 32, b2[0], b2[1], b2[2], b2[3]);

#pragma unroll
            for (int mi = 0; mi < 2; mi++) {
#pragma unroll
                for (int j = 0; j < 6; j++) {
                    float* d = acc[mi][j];
                    mma_f16(d[0], d[1], d[2], d[3],
                            ah[mi][0], ah[mi][1], ah[mi][2], ah[mi][3],
                            bh[j >> 1][2 * (j & 1)], bh[j >> 1][2 * (j & 1) + 1]);
                }
                if (NT == 7) {
                    float* d = acc[mi][6];
                    mma_f16(d[0], d[1], d[2], d[3],
                            ah[mi][0], ah[mi][1], ah[mi][2], ah[mi][3],
                            b2[0], b2[1]);
                }
            }
        }

        BAR_ARRIVE(5 + slot);          // slot empty
    }

    // write live partials
#pragma unroll
    for (int mi = 0; mi < 2; mi++)
#pragma unroll
        for (int j = 0; j < NT; j++) {
            const int colb = wn * 48 + j * 8;
#pragma unroll
            for (int e = 0; e < 4; e++) {
                const int r = m0 + wm * 32 + mi * 16 + (lane >> 2) + (e >> 1) * 8;
                const int c = colb + (lane & 3) * 2 + (e & 1);
                g_part[((size_t)split * Bdim + r) * CPAD + c] = acc[mi][j][e];
            }
        }
}

// ======================= warp-specialized HMMA fp16 GEMM =======================
// grid (Bdim/BM, SPLITS), 512 threads.
// Warps 0-7 consumers: wm = w&3 (SMSP), wn = w>>2 in {0,1}.
// Warps 8-15 producers: thread pt = t-256; row = pt>>1, half = pt&1 (32 floats).
__global__ void __launch_bounds__(512, 1)
gemm_mma_kernel(const float* __restrict__ F) {
    extern __shared__ char smem[];
    const uint32_t sbase = smem_u32(smem);

    const int t     = threadIdx.x;
    const int lane  = t & 31;
    const int w     = t >> 5;
    const int m0    = blockIdx.x * BM;
    const int split = blockIdx.y;
    const int k0    = split * KC;

    if (w >= 8) {
        // ===================== PRODUCER =====================
        const int pt   = t - 256;             // 0..255
        const int row  = pt >> 1;             // 0..127
        const int half = pt & 1;              // 0/1 (32 floats each)

        const float4* gA = (const float4*)(F + (size_t)(m0 + row) * Ddim + k0);
        const char* srcB = (const char*)g_wh + (size_t)row * (W32 * 4) + (size_t)k0 * 2
                         + half * 64;
        const uint32_t stsA = row * STR + half * 64;
        const uint32_t dstB = TILE_SZ + row * STR + half * 64;

        float nf = 0.f;

        for (int it = 0; it < ITERS; it++) {
            const int slot = it & 3;
            const uint32_t sb = sbase + slot * SLOT_SZ;

            if (it >= NSLOT) BAR_SYNC(5 + slot);        // wait consumers freed slot

            // B: 64 B via 4x cp.async
            const char* s = srcB + (size_t)it * 128;
#pragma unroll
            for (int c = 0; c < 4; c++) CP16(sb + dstB + c * 16, s + c * 16);
            CP_COMMIT();

            // A: 32 floats (8x LDG.128, MLP=8) -> 16 f16x2 -> 4 STS.128
            float4 v[8];
#pragma unroll
            for (int j = 0; j < 8; j++) v[j] = gA[it * 16 + half * 8 + j];
#pragma unroll
            for (int c = 0; c < 2; c++) {
                uint32_t pk[8];
#pragma unroll
                for (int j = 0; j < 4; j++) {
                    float4 x = v[c * 4 + j];
                    nf += x.x * x.x + x.y * x.y + x.z * x.z + x.w * x.w;
                    pk[2 * j]     = cvt_f16x2(x.x, x.y);
                    pk[2 * j + 1] = cvt_f16x2(x.z, x.w);
                }
                *(uint4*)(smem + slot * SLOT_SZ + stsA + c * 32)      =
                    make_uint4(pk[0], pk[1], pk[2], pk[3]);
                *(uint4*)(smem + slot * SLOT_SZ + stsA + c * 32 + 16) =
                    make_uint4(pk[4], pk[5], pk[6], pk[7]);
            }

            CP_WAIT0();                // B in smem
            BAR_ARRIVE(1 + slot);      // slot full
        }
        g_nfsq[(split * 2 + half) * Bdim + m0 + row] = nf;
        return;
    }

    // ===================== CONSUMER =====================
    const int wm = w & 3;
    const int wn = w >> 2;             // 0..1

    const uint32_t aRel  = (wm * 32 + (lane & 15)) * STR + (lane >> 4) * 16;
    const uint32_t bLane = (lane & 7) + ((lane >> 4) << 3);
    const uint32_t bOff  = (((lane >> 3) & 1) << 4);
    const uint32_t bRelBase = TILE_SZ + (wn * 48 + bLane) * STR + bOff;
    const uint32_t bRelLone = TILE_SZ + (96 + bLane) * STR + bOff;

    if (wn == 0)
        consumer_loop<6>(sbase, aRel, bRelBase, bRelLone, m0, split, wm, wn, lane);
    else
        consumer_loop<7>(sbase, aRel, bRelBase, bRelLone, m0, split, wm, wn, lane);
}

// ======================= per-row epilogue + fused finalize =======================
__global__ __launch_bounds__(128) void epilogue_kernel(const void* __restrict__ labels,
                                                       float* __restrict__ out,
                                                       int out_size) {
    const int row = blockIdx.x;
    const int t   = threadIdx.x;

    __shared__ float sv[128];
    __shared__ int   si[128];
    __shared__ float slog[128];
    __shared__ float s_nf;
    __shared__ int   s_ok[2];
    __shared__ unsigned s_tick;

    // int64-vs-int32 label layout sniff
    if (t < 64) {
        const int hi = ((const int*)labels)[2 * t + 1];
        const int ok = (hi == 0 || hi == -1) ? 1 : 0;
        unsigned b = __ballot_sync(0xFFFFFFFFu, ok);
        if ((t & 31) == 0) s_ok[t >> 5] = (b == 0xFFFFFFFFu);
    }

    // feature-norm reduction (warp 2, 16 partials)
    if (t >= 64 && t < 96) {
        const int l = t - 64;
        float s = (l < 2 * SPLITS) ? g_nfsq[l * Bdim + row] : 0.f;
#pragma unroll
        for (int off = 16; off > 0; off >>= 1)
            s += __shfl_down_sync(0xFFFFFFFFu, s, off);
        if (l == 0) s_nf = fmaxf(sqrtf(s), 1e-8f);
    }

    float g = 0.f;
    if (t < Cdim) {
#pragma unroll
        for (int s = 0; s < SPLITS; s++)
            g += g_part[((size_t)s * Bdim + row) * CPAD + t];
    }
    __syncthreads();

    const float logit = (t < Cdim) ? 10.0f * g / s_nf : -CUDART_INF_F;
    slog[t] = logit;
    sv[t]   = logit;
    si[t]   = t;
    __syncthreads();

    for (int off = 64; off > 0; off >>= 1) {
        if (t < off) {
            float v2 = sv[t + off]; int i2 = si[t + off];
            if (v2 > sv[t] || (v2 == sv[t] && i2 < si[t])) { sv[t] = v2; si[t] = i2; }
        }
        __syncthreads();
    }
    const float mx   = sv[0];
    const int   amax = si[0];
    __syncthreads();

    sv[t] = (t < Cdim) ? expf(logit - mx) : 0.f;
    __syncthreads();
    for (int off = 64; off > 0; off >>= 1) {
        if (t < off) sv[t] += sv[t + off];
        __syncthreads();
    }

    if (t == 0) {
        const float lse = logf(sv[0]) + mx;
        const int is64 = (s_ok[0] && s_ok[1]) ? 1 : 0;
        long long lab;
        if (is64) lab = ((const long long*)labels)[row];
        else      lab = (long long)((const int*)labels)[row];
        if (lab >= 0) {
            const float nll = lse - slog[(int)lab];
            // fixed-point (2^-32) integer accumulate: order-independent, deterministic
            const unsigned long long fx =
                (unsigned long long)(fmax((double)nll, 0.0) * 4294967296.0 + 0.5);
            atomicAdd(&g_loss_fx, fx);
            if (amax == (int)lab) atomicAdd(&g_corr_acc, 1);
            atomicAdd(&g_vld_acc, 1);
        }
        __threadfence();
        s_tick = atomicAdd(&g_ticket, 1u);
    }
    __syncthreads();

    // last block finalizes
    if (s_tick == (unsigned)(gridDim.x - 1) && t == 0) {
        const double loss_sum = (double)g_loss_fx * (1.0 / 4294967296.0);
        const float nv = (float)g_vld_acc;
        out[0] = (float)(loss_sum / (double)fmaxf(nv, 1.0f));
        if (out_size > 1) out[1] = (float)g_corr_acc / (nv + 1e-10f);
    }
}

// ======================= launch =======================
extern "C" void kernel_launch(void* const* d_in, const int* in_sizes, int n_in,
                              void* d_out, int out_size) {
    int fi = 0, li = 0;
    for (int i = 1; i < n_in; i++) {
        if (in_sizes[i] > in_sizes[fi]) fi = i;
        if (in_sizes[i] < in_sizes[li]) li = i;
    }
    int wi = 0;
    for (int i = 0; i < n_in; i++) if (i != fi && i != li) wi = i;

    const float* F = (const float*)d_in[fi];
    const float* W = (const float*)d_in[wi];
    const void*  L = d_in[li];

    cudaFuncSetAttribute(gemm_mma_kernel,
                         cudaFuncAttributeMaxDynamicSharedMemorySize, SMEM_TOTAL);

    prep_w_kernel<<<CPAD, 1024>>>(W);
    gemm_mma_kernel<<<dim3(Bdim / BM, SPLITS), 512, SMEM_TOTAL>>>(F);
    epilogue_kernel<<<Bdim, 128>>>(L, (float*)d_out, out_size);
}

// round 10
// speedup vs baseline: 1.6582x; 1.4101x over previous
#include <cuda_runtime.h>
#include <math_constants.h>
#include <cstdint>

// Problem shape (fixed)
#define Bdim 2048
#define Ddim 25088
#define Cdim 100
#define CPAD 128

#define KT 64                   // fp16 K per iteration
#define NKT (Ddim / KT)         // 392 total k-tiles
#define BM 128
#define MAXS 10                 // max k-splits per m-tile

// smem tile geometry: 128 rows x 64 fp16 (128 B), row stride padded to 144 B
#define STR 144
#define TILE_SZ (128 * STR)              // 18432 B
#define BUF_SZ (2 * TILE_SZ)             // A, B
#define SMEM_TOTAL (2 * BUF_SZ)          // 73728 B

#define W32 12544                        // u32 per W row (25088 fp16)

// ---------------- scratch ----------------
__device__ float    g_part[(size_t)MAXS * Bdim * CPAD];   // 10.5 MB split partials
__device__ float    g_nfsq[MAXS * 4 * Bdim];              // feature norm^2 partials
__device__ uint32_t g_wh[(size_t)CPAD * W32];             // raw W, fp16 (rows>=100 stay 0)
__device__ float    g_wnsq[CPAD];                         // weight row norm^2
__device__ unsigned long long g_loss_fx;                  // fixed-point loss sum (2^-32)
__device__ int      g_corr_acc;
__device__ int      g_vld_acc;
__device__ unsigned g_ticket;

// ---------------- helpers ----------------
__device__ __forceinline__ uint32_t smem_u32(const void* p) {
    uint32_t a;
    asm("{ .reg .u64 t; cvta.to.shared.u64 t, %1; cvt.u32.u64 %0, t; }" : "=r"(a) : "l"(p));
    return a;
}
__device__ __forceinline__ void ldsm4(uint32_t addr, uint32_t& r0, uint32_t& r1,
                                      uint32_t& r2, uint32_t& r3) {
    asm volatile("ldmatrix.sync.aligned.m8n8.x4.shared.b16 {%0,%1,%2,%3}, [%4];"
                 : "=r"(r0), "=r"(r1), "=r"(r2), "=r"(r3) : "r"(addr));
}
__device__ __forceinline__ void mma_f16(float& d0, float& d1, float& d2, float& d3,
                                        uint32_t a0, uint32_t a1, uint32_t a2, uint32_t a3,
                                        uint32_t b0, uint32_t b1) {
    asm volatile("mma.sync.aligned.m16n8k16.row.col.f32.f16.f16.f32 "
                 "{%0,%1,%2,%3}, {%4,%5,%6,%7}, {%8,%9}, {%0,%1,%2,%3};"
                 : "+f"(d0), "+f"(d1), "+f"(d2), "+f"(d3)
                 : "r"(a0), "r"(a1), "r"(a2), "r"(a3), "r"(b0), "r"(b1));
}
__device__ __forceinline__ uint32_t cvt_f16x2(float x, float y) {
    uint32_t r;
    asm("cvt.rn.f16x2.f32 %0, %1, %2;" : "=r"(r) : "f"(y), "f"(x));
    return r;
}
#define CP16(dst, src) asm volatile("cp.async.cg.shared.global [%0], [%1], 16;" :: "r"(dst), "l"(src))
#define CP_COMMIT()    asm volatile("cp.async.commit_group;" ::: "memory")
#define CP_WAIT1()     asm volatile("cp.async.wait_group 1;" ::: "memory")
#define CP_WAIT0()     asm volatile("cp.async.wait_group 0;" ::: "memory")

// ======================= W prep: one pass, raw fp16 + norm^2 ====================
// grid 100 blocks (rows >= 100 of g_wh stay statically zero).
__global__ __launch_bounds__(256) void prep_w_kernel(const float* __restrict__ W) {
    const int row = blockIdx.x;                // 0..99
    const int t   = threadIdx.x;
    __shared__ float red[256];

    if (row == 0 && t == 0) {
        g_loss_fx = 0ull; g_corr_acc = 0; g_vld_acc = 0; g_ticket = 0u;
    }

    const float4* r4 = (const float4*)(W + (size_t)row * Ddim);
    uint2* dh = (uint2*)&g_wh[(size_t)row * W32];
    float s = 0.f;
    for (int i = t; i < Ddim / 4; i += 256) {
        float4 v = r4[i];
        s += v.x * v.x + v.y * v.y + v.z * v.z + v.w * v.w;
        dh[i] = make_uint2(cvt_f16x2(v.x, v.y), cvt_f16x2(v.z, v.w));
    }
    red[t] = s;
    __syncthreads();
    for (int off = 128; off > 0; off >>= 1) {
        if (t < off) red[t] += red[t + off];
        __syncthreads();
    }
    if (t == 0) g_wnsq[row] = red[0];
}

// ======================= HMMA fp16 GEMM (148 CTAs, uneven split-K) =============
// grid 148, 512 threads. Warps: wm = w&3 (SMSP), wn = w>>2; wn==3 -> 1 n8 group.
__global__ void __launch_bounds__(512, 1)
gemm_mma_kernel(const float* __restrict__ F) {
    extern __shared__ char smem[];
    const uint32_t sbase = smem_u32(smem);

    // block -> (m-tile, split)
    const int bid = blockIdx.x;
    int mt, s, S;
    if (bid < 108) { mt = bid / 9;  s = bid - mt * 9;          S = 9; }
    else           { int b2 = bid - 108; mt = 12 + b2 / 10; s = b2 % 10; S = 10; }
    const int base = NKT / S, rem = NKT % S;
    const int nt   = base + (s < rem ? 1 : 0);
    const int kt0  = s * base + (s < rem ? s : rem);
    const int m0   = mt * BM;
    const int k0   = kt0 * KT;

    const int t    = threadIdx.x;
    const int lane = t & 31;
    const int w    = t >> 5;

    // ---- loader mapping: row = t/4, q = t&3 covers 16 floats (32 B fp16) ----
    const int row = t >> 2;
    const int q   = t & 3;

    const float4* gA = (const float4*)(F + (size_t)(m0 + row) * Ddim + k0) + q * 4;
    const uint32_t stsA_off = row * STR + q * 32;
    const char* srcB = (const char*)g_wh + (size_t)row * (W32 * 4) + (size_t)k0 * 2 + q * 32;
    const uint32_t dstB_off = TILE_SZ + row * STR + q * 32;

    // ---- MMA mapping ----
    const int wm = w & 3;
    const int wn = w >> 2;
    const int nmax = (wn == 3) ? 1 : 4;
    const uint32_t aAddr0 = sbase + (wm * 32 + (lane & 15)) * STR + (lane >> 4) * 16;
    const uint32_t bAddr0 = sbase + TILE_SZ +
        (wn * 32 + (lane & 7) + (lane >> 4) * 8) * STR + ((lane >> 3) & 1) * 16;

    float acc[2][4][4];
#pragma unroll
    for (int i = 0; i < 2; i++)
#pragma unroll
        for (int j = 0; j < 4; j++)
#pragma unroll
            for (int e = 0; e < 4; e++) acc[i][j][e] = 0.f;

    float nf = 0.f;
    float4 ra[4];

    // prologue: A tile 0 into regs; B tile 0 cp.async into buf0
#pragma unroll
    for (int j = 0; j < 4; j++) ra[j] = gA[j];
    CP16(sbase + dstB_off, srcB);
    CP16(sbase + dstB_off + 16, srcB + 16);
    CP_COMMIT();

    for (int it = 0; it < nt; it++) {
        const uint32_t bufo = (it & 1) ? BUF_SZ : 0;
        const uint32_t nbuf = (it & 1) ? 0 : BUF_SZ;

        __syncthreads();   // buf writable (prior MMA reads done)

        // issue B(it+1) into other buffer
        if (it + 1 < nt) {
            const char* sB = srcB + (size_t)(it + 1) * 128;
            CP16(sbase + nbuf + dstB_off, sB);
            CP16(sbase + nbuf + dstB_off + 16, sB + 16);
            CP_COMMIT();
        }

        // convert + store A tile `it` (16 floats -> 8 f16x2 -> 2 STS.128)
        {
            uint32_t pk[8];
#pragma unroll
            for (int j = 0; j < 4; j++) {
                float4 v = ra[j];
                nf += v.x * v.x + v.y * v.y + v.z * v.z + v.w * v.w;
                pk[2 * j]     = cvt_f16x2(v.x, v.y);
                pk[2 * j + 1] = cvt_f16x2(v.z, v.w);
            }
            *(uint4*)(smem + bufo + stsA_off)      = make_uint4(pk[0], pk[1], pk[2], pk[3]);
            *(uint4*)(smem + bufo + stsA_off + 16) = make_uint4(pk[4], pk[5], pk[6], pk[7]);
        }

        // single-stage A prefetch (covered by the MMA phase)
        if (it + 1 < nt) {
#pragma unroll
            for (int j = 0; j < 4; j++) ra[j] = gA[(it + 1) * 16 + j];
        }

        if (it + 1 < nt) { CP_WAIT1(); } else { CP_WAIT0(); }
        __syncthreads();   // tile `it` fully visible

        // MMA: 4 k16 steps
#pragma unroll
        for (int ks = 0; ks < 4; ks++) {
            uint32_t ah[2][4], bh[2][4];
#pragma unroll
            for (int mi = 0; mi < 2; mi++) {
                const uint32_t a = aAddr0 + bufo + mi * 16 * STR + ks * 32;
                ldsm4(a, ah[mi][0], ah[mi][1], ah[mi][2], ah[mi][3]);
            }
            {
                const uint32_t b = bAddr0 + bufo + ks * 32;
                ldsm4(b, bh[0][0], bh[0][1], bh[0][2], bh[0][3]);
                if (nmax == 4)
                    ldsm4(b + 16 * STR, bh[1][0], bh[1][1], bh[1][2], bh[1][3]);
            }
#pragma unroll
            for (int mi = 0; mi < 2; mi++)
#pragma unroll
                for (int nj = 0; nj < 4; nj++) {
                    if (nj >= nmax) break;
                    float* d = acc[mi][nj];
                    mma_f16(d[0], d[1], d[2], d[3],
                            ah[mi][0], ah[mi][1], ah[mi][2], ah[mi][3],
                            bh[nj >> 1][2 * (nj & 1)], bh[nj >> 1][2 * (nj & 1) + 1]);
                }
        }
    }

    // feature norm^2 partial (slot s, quarter q)
    g_nfsq[(s * 4 + q) * Bdim + (m0 + row)] = nf;

    // write live partials into split slot s
#pragma unroll
    for (int mi = 0; mi < 2; mi++)
#pragma unroll
        for (int nj = 0; nj < 4; nj++) {
            if (nj >= nmax) break;
#pragma unroll
            for (int e = 0; e < 4; e++) {
                const int r = m0 + wm * 32 + mi * 16 + (lane >> 2) + (e >> 1) * 8;
                const int c = wn * 32 + nj * 8 + (lane & 3) * 2 + (e & 1);
                g_part[((size_t)s * Bdim + r) * CPAD + c] = acc[mi][nj][e];
            }
        }
}

// ======================= warp-per-row epilogue + fused finalize ==================
// grid 256 blocks x 256 threads; warp w handles row = bid*8 + w. No block syncs.
__global__ __launch_bounds__(256) void epilogue_kernel(const void* __restrict__ labels,
                                                       float* __restrict__ out,
                                                       int out_size) {
    const int t    = threadIdx.x;
    const int lane = t & 31;
    const int row  = blockIdx.x * 8 + (t >> 5);

    // int64-vs-int32 label layout sniff (per warp; global property)
    const int hiw = ((const int*)labels)[2 * lane + 1];
    const unsigned bal = __ballot_sync(0xFFFFFFFFu, (hiw == 0) || (hiw == -1));
    const int is64 = (bal == 0xFFFFFFFFu);

    const int mt = row >> 7;
    const int S  = (mt < 12) ? 9 : 10;
    const int n4 = 4 * S;

    // feature norm
    float nf = (lane < n4) ? g_nfsq[lane * Bdim + row] : 0.f;
    if (lane < n4 - 32) nf += g_nfsq[(32 + lane) * Bdim + row];
#pragma unroll
    for (int o = 16; o > 0; o >>= 1) nf += __shfl_xor_sync(0xFFFFFFFFu, nf, o);
    const float fninv = 10.0f / fmaxf(sqrtf(nf), 1e-8f);

    // logits (4 per lane: cols lane+32j)
    float lg[4];
#pragma unroll
    for (int j = 0; j < 4; j++) {
        const int c = lane + 32 * j;
        if (c < Cdim) {
            float g = 0.f;
            for (int s2 = 0; s2 < S; s2++)
                g += g_part[((size_t)s2 * Bdim + row) * CPAD + c];
            lg[j] = g * fninv / fmaxf(sqrtf(g_wnsq[c]), 1e-8f);
        } else {
            lg[j] = -CUDART_INF_F;
        }
    }

    // max + first-index argmax
    float mv = lg[0]; int mi = lane;
#pragma unroll
    for (int j = 1; j < 4; j++)
        if (lg[j] > mv) { mv = lg[j]; mi = lane + 32 * j; }
#pragma unroll
    for (int o = 16; o > 0; o >>= 1) {
        const float ov = __shfl_xor_sync(0xFFFFFFFFu, mv, o);
        const int   oi = __shfl_xor_sync(0xFFFFFFFFu, mi, o);
        if (ov > mv || (ov == mv && oi < mi)) { mv = ov; mi = oi; }
    }

    // log-sum-exp
    float es = 0.f;
#pragma unroll
    for (int j = 0; j < 4; j++)
        if (lane + 32 * j < Cdim) es += expf(lg[j] - mv);
#pragma unroll
    for (int o = 16; o > 0; o >>= 1) es += __shfl_xor_sync(0xFFFFFFFFu, es, o);
    const float lse = logf(es) + mv;

    // label (lane 0 loads, broadcast)
    int labi0 = 0;
    if (lane == 0) {
        long long lab = is64 ? ((const long long*)labels)[row]
                             : (long long)((const int*)labels)[row];
        labi0 = (int)lab;
    }
    const int labi = __shfl_sync(0xFFFFFFFFu, labi0, 0);

    if (labi >= 0) {
        const int sl = labi & 31, jj = labi >> 5;
        const float cand = (jj == 0) ? lg[0] : (jj == 1) ? lg[1] : (jj == 2) ? lg[2] : lg[3];
        const float lv = __shfl_sync(0xFFFFFFFFu, cand, sl);
        if (lane == 0) {
            const float nll = lse - lv;
            const unsigned long long fx =
                (unsigned long long)(fmax((double)nll, 0.0) * 4294967296.0 + 0.5);
            atomicAdd(&g_loss_fx, fx);
            if (mi == labi) atomicAdd(&g_corr_acc, 1);
            atomicAdd(&g_vld_acc, 1);
        }
    }

    if (lane == 0) {
        __threadfence();
        const unsigned tk = atomicAdd(&g_ticket, 1u);
        if (tk == (unsigned)(Bdim - 1)) {
            // atomic reads: guaranteed fresh from L2
            const unsigned long long ls = atomicAdd(&g_loss_fx, 0ull);
            const int cr = atomicAdd(&g_corr_acc, 0);
            const int vl = atomicAdd(&g_vld_acc, 0);
            const double loss_sum = (double)ls * (1.0 / 4294967296.0);
            const float nv = (float)vl;
            out[0] = (float)(loss_sum / (double)fmaxf(nv, 1.0f));
            if (out_size > 1) out[1] = (float)cr / (nv + 1e-10f);
        }
    }
}

// ======================= launch =======================
extern "C" void kernel_launch(void* const* d_in, const int* in_sizes, int n_in,
                              void* d_out, int out_size) {
    int fi = 0, li = 0;
    for (int i = 1; i < n_in; i++) {
        if (in_sizes[i] > in_sizes[fi]) fi = i;
        if (in_sizes[i] < in_sizes[li]) li = i;
    }
    int wi = 0;
    for (int i = 0; i < n_in; i++) if (i != fi && i != li) wi = i;

    const float* F = (const float*)d_in[fi];
    const float* W = (const float*)d_in[wi];
    const void*  L = d_in[li];

    cudaFuncSetAttribute(gemm_mma_kernel,
                         cudaFuncAttributeMaxDynamicSharedMemorySize, SMEM_TOTAL);

    prep_w_kernel<<<Cdim, 256>>>(W);
    gemm_mma_kernel<<<148, 512, SMEM_TOTAL>>>(F);
    epilogue_kernel<<<Bdim / 8, 256>>>(L, (float*)d_out, out_size);
}